// round 5
// baseline (speedup 1.0000x reference)
#include <cuda_runtime.h>
#include <cuda_bf16.h>

#define N_NODES 50000
#define N_EDGES 800000
#define DIM     256
#define HID     128
#define NTHR    256
#define SCAN_B  1024
#define NB_SCAN ((N_NODES + SCAN_B - 1) / SCAN_B)   // 49

#define TM      64                 // nodes per block in node_weight
#define LDK     264                // padded bf16 row stride (256 + 8)
#define NW_SMEM (2 * TM * LDK * 2) // two bf16 planes, bytes = 67584

__device__ float g_wnode[N_NODES];
__device__ int   g_is64;
__device__ int   g_cnt[N_NODES];
__device__ int   g_incl[N_NODES];
__device__ int   g_btot[64];
__device__ int   g_start[N_NODES + 1];
__device__ int   g_cur[N_NODES + 1];
__device__ int   g_scol[N_EDGES];
__device__ __nv_bfloat16 g_w1th[HID * DIM];   // W1^T hi: [n][k]
__device__ __nv_bfloat16 g_w1tl[HID * DIM];   // W1^T lo: [n][k]

// ---------------------------------------------------------------------------
__device__ __forceinline__ int load_idx(const void* ei, long long pos, bool is64) {
    int v = is64 ? (int)((const long long*)ei)[pos] : ((const int*)ei)[pos];
    return min(max(v, 0), N_NODES - 1);
}

// ---------------------------------------------------------------------------
__global__ void detect_kernel(const int* __restrict__ ei32) {
    int all_hi_zero = 1;
    #pragma unroll 8
    for (int i = 0; i < 512; ++i)
        if (ei32[2 * i + 1] != 0) { all_hi_zero = 0; break; }
    g_is64 = all_hi_zero;
}

__global__ void zero_cnt_kernel() {
    int i = blockIdx.x * blockDim.x + threadIdx.x;
    if (i < N_NODES) g_cnt[i] = 0;
}

// ---------------------------------------------------------------------------
// W1 -> transposed bf16 hi/lo planes ([n][k], so B fragments are contiguous-k)
// ---------------------------------------------------------------------------
__global__ void prep_w1_kernel(const float* __restrict__ W1) {
    int i = blockIdx.x * blockDim.x + threadIdx.x;   // i over HID*DIM
    if (i >= HID * DIM) return;
    int n = i >> 8;          // /DIM
    int k = i & (DIM - 1);
    float v = W1[k * HID + n];
    __nv_bfloat16 h = __float2bfloat16(v);
    __nv_bfloat16 l = __float2bfloat16(v - __bfloat162float(h));
    g_w1th[n * DIM + k] = h;
    g_w1tl[n * DIM + k] = l;
}

// ---------------------------------------------------------------------------
// CSR build: count, scan, fill.
// ---------------------------------------------------------------------------
__global__ void count_kernel(const void* __restrict__ ei) {
    int e = blockIdx.x * blockDim.x + threadIdx.x;
    if (e >= N_EDGES) return;
    int row = load_idx(ei, e, g_is64 != 0);
    atomicAdd(&g_cnt[row], 1);
}

__global__ void scan1_kernel() {      // per-block inclusive scan, shuffle-based
    __shared__ int s_wt[32];
    const int t = threadIdx.x, b = blockIdx.x;
    const int lane = t & 31, wid = t >> 5;
    const int i = b * SCAN_B + t;
    int v = (i < N_NODES) ? g_cnt[i] : 0;
    int sv = v;
    #pragma unroll
    for (int off = 1; off < 32; off <<= 1) {
        int u = __shfl_up_sync(0xffffffffu, sv, off);
        if (lane >= off) sv += u;
    }
    if (lane == 31) s_wt[wid] = sv;
    __syncthreads();
    if (wid == 0) {
        int wv = (lane < 32) ? s_wt[lane] : 0;
        #pragma unroll
        for (int off = 1; off < 32; off <<= 1) {
            int u = __shfl_up_sync(0xffffffffu, wv, off);
            if (lane >= off) wv += u;
        }
        s_wt[lane] = wv;
    }
    __syncthreads();
    int incl = sv + ((wid > 0) ? s_wt[wid - 1] : 0);
    if (i < N_NODES) g_incl[i] = incl;
    if (t == SCAN_B - 1) g_btot[b] = incl;
}

__global__ void scan2_kernel() {      // exclusive scan of 49 block totals
    if (threadIdx.x == 0) {
        int run = 0;
        #pragma unroll 1
        for (int b = 0; b < NB_SCAN; ++b) {
            int t = g_btot[b];
            g_btot[b] = run;
            run += t;
        }
    }
}

__global__ void scan3_kernel() {
    int i = blockIdx.x * blockDim.x + threadIdx.x;
    if (i >= N_NODES) return;
    int v = g_incl[i] + g_btot[i >> 10];
    g_start[i + 1] = v;
    g_cur[i + 1]   = v;
    if (i == 0) { g_start[0] = 0; g_cur[0] = 0; }
}

__global__ void fill_kernel(const void* __restrict__ ei) {
    int e = blockIdx.x * blockDim.x + threadIdx.x;
    if (e >= N_EDGES) return;
    bool is64 = (g_is64 != 0);
    int row = load_idx(ei, e, is64);
    int col = load_idx(ei, (long long)N_EDGES + e, is64);
    int pos = atomicAdd(&g_cur[row], 1);
    g_scol[pos] = col;
}

// ---------------------------------------------------------------------------
// Node attention weights via bf16 split-precision mma.sync (HMMA).
// Block = 64 nodes, 8 warps: 4 M-warps (16 rows) x 2 N-warps (64 hid cols).
// D = (Ah+Al)(Bh+Bl) with 4 mma products, f32 accumulate -> ~fp32 accuracy.
// ---------------------------------------------------------------------------
__device__ __forceinline__ void mma_bf16(float* c, const unsigned* a,
                                         unsigned b0, unsigned b1) {
    asm volatile(
        "mma.sync.aligned.m16n8k16.row.col.f32.bf16.bf16.f32 "
        "{%0,%1,%2,%3}, {%4,%5,%6,%7}, {%8,%9}, {%0,%1,%2,%3};"
        : "+f"(c[0]), "+f"(c[1]), "+f"(c[2]), "+f"(c[3])
        : "r"(a[0]), "r"(a[1]), "r"(a[2]), "r"(a[3]), "r"(b0), "r"(b1));
}

__global__ __launch_bounds__(NTHR)
void node_weight_kernel(const float* __restrict__ x,
                        const float* __restrict__ b1,
                        const float* __restrict__ W2,
                        const float* __restrict__ b2)
{
    extern __shared__ __nv_bfloat16 dsm[];
    __nv_bfloat16* sxh = dsm;                 // [TM][LDK]
    __nv_bfloat16* sxl = dsm + TM * LDK;

    __shared__ float s_red[2][TM];
    __shared__ float s_b1[HID];
    __shared__ float s_w2[HID];

    const int tid  = threadIdx.x;
    const int lane = tid & 31;
    const int wid  = tid >> 5;
    const int wm   = wid >> 1;        // 0..3  -> rows [wm*16, +16)
    const int wn   = wid & 1;         // 0..1  -> hid cols [wn*64, +64)
    const int base = blockIdx.x * TM;

    if (tid < HID) {
        s_b1[tid] = __ldg(&b1[tid]);
        s_w2[tid] = __ldg(&W2[tid]);
    }

    // --- stage x tile: fp32 -> bf16 hi/lo planes in smem ---
    #pragma unroll
    for (int it = 0; it < (TM * (DIM / 4)) / NTHR; ++it) {
        int f = it * NTHR + tid;
        int row = f >> 6;
        int q = f & 63;
        int node = min(base + row, N_NODES - 1);
        float4 v = __ldg(((const float4*)(x + (long long)node * DIM)) + q);
        __nv_bfloat16 h0 = __float2bfloat16(v.x);
        __nv_bfloat16 h1 = __float2bfloat16(v.y);
        __nv_bfloat16 h2 = __float2bfloat16(v.z);
        __nv_bfloat16 h3 = __float2bfloat16(v.w);
        __nv_bfloat16 l0 = __float2bfloat16(v.x - __bfloat162float(h0));
        __nv_bfloat16 l1 = __float2bfloat16(v.y - __bfloat162float(h1));
        __nv_bfloat16 l2 = __float2bfloat16(v.z - __bfloat162float(h2));
        __nv_bfloat16 l3 = __float2bfloat16(v.w - __bfloat162float(h3));
        __nv_bfloat162 hh01 = __halves2bfloat162(h0, h1);
        __nv_bfloat162 hh23 = __halves2bfloat162(h2, h3);
        __nv_bfloat162 ll01 = __halves2bfloat162(l0, l1);
        __nv_bfloat162 ll23 = __halves2bfloat162(l2, l3);
        int o = row * LDK + q * 4;
        *(__nv_bfloat162*)&sxh[o]     = hh01;
        *(__nv_bfloat162*)&sxh[o + 2] = hh23;
        *(__nv_bfloat162*)&sxl[o]     = ll01;
        *(__nv_bfloat162*)&sxl[o + 2] = ll23;
    }
    __syncthreads();

    // --- GEMM: 16 k-steps, 8 n-tiles, 4 split products each ---
    float acc[8][4];
    #pragma unroll
    for (int nt = 0; nt < 8; ++nt)
        #pragma unroll
        for (int c = 0; c < 4; ++c) acc[nt][c] = 0.f;

    const int r0  = wm * 16 + (lane >> 2);
    const int klo = (lane & 3) * 2;
    const unsigned* W1h32 = (const unsigned*)g_w1th;
    const unsigned* W1l32 = (const unsigned*)g_w1tl;

    #pragma unroll 1
    for (int ks = 0; ks < DIM / 16; ++ks) {
        const int k = ks * 16 + klo;
        unsigned ah[4], al[4];
        ah[0] = *(const unsigned*)&sxh[r0 * LDK + k];
        ah[1] = *(const unsigned*)&sxh[(r0 + 8) * LDK + k];
        ah[2] = *(const unsigned*)&sxh[r0 * LDK + k + 8];
        ah[3] = *(const unsigned*)&sxh[(r0 + 8) * LDK + k + 8];
        al[0] = *(const unsigned*)&sxl[r0 * LDK + k];
        al[1] = *(const unsigned*)&sxl[(r0 + 8) * LDK + k];
        al[2] = *(const unsigned*)&sxl[r0 * LDK + k + 8];
        al[3] = *(const unsigned*)&sxl[(r0 + 8) * LDK + k + 8];

        #pragma unroll
        for (int nt = 0; nt < 8; ++nt) {
            const int n0 = wn * 64 + nt * 8 + (lane >> 2);
            const int bo = (n0 * DIM + ks * 16 + klo) >> 1;   // uint32 index
            unsigned bh0 = __ldg(&W1h32[bo]);
            unsigned bh1 = __ldg(&W1h32[bo + 4]);
            unsigned bl0 = __ldg(&W1l32[bo]);
            unsigned bl1 = __ldg(&W1l32[bo + 4]);
            mma_bf16(acc[nt], ah, bh0, bh1);
            mma_bf16(acc[nt], ah, bl0, bl1);
            mma_bf16(acc[nt], al, bh0, bh1);
            mma_bf16(acc[nt], al, bl0, bl1);
        }
    }

    // --- epilogue: relu(+b1) . W2 per row, reduce across lanes & N-warps ---
    float sA = 0.f, sB = 0.f;
    #pragma unroll
    for (int nt = 0; nt < 8; ++nt) {
        int j0 = wn * 64 + nt * 8 + (lane & 3) * 2;
        float bb0 = s_b1[j0],  bb1 = s_b1[j0 + 1];
        float ww0 = s_w2[j0],  ww1 = s_w2[j0 + 1];
        sA = fmaf(fmaxf(acc[nt][0] + bb0, 0.f), ww0, sA);
        sA = fmaf(fmaxf(acc[nt][1] + bb1, 0.f), ww1, sA);
        sB = fmaf(fmaxf(acc[nt][2] + bb0, 0.f), ww0, sB);
        sB = fmaf(fmaxf(acc[nt][3] + bb1, 0.f), ww1, sB);
    }
    sA += __shfl_xor_sync(0xffffffffu, sA, 1);
    sA += __shfl_xor_sync(0xffffffffu, sA, 2);
    sB += __shfl_xor_sync(0xffffffffu, sB, 1);
    sB += __shfl_xor_sync(0xffffffffu, sB, 2);

    if ((lane & 3) == 0) {
        s_red[wn][wm * 16 + (lane >> 2)]     = sA;
        s_red[wn][wm * 16 + 8 + (lane >> 2)] = sB;
    }
    __syncthreads();

    if (tid < TM) {
        int node = base + tid;
        if (node < N_NODES) {
            float logit = s_red[0][tid] + s_red[1][tid] + __ldg(b2);
            g_wnode[node] = 1.f / (1.f + expf(-logit));
        }
    }
}

// ---------------------------------------------------------------------------
// Aggregation: one warp per destination node (unchanged from R4 winner).
// ---------------------------------------------------------------------------
__global__ __launch_bounds__(NTHR, 8)
void agg_kernel(const float* __restrict__ x, float* __restrict__ out)
{
    const int warp = (blockIdx.x * NTHR + threadIdx.x) >> 5;
    const int lane = threadIdx.x & 31;
    if (warp >= N_NODES) return;

    const int s = g_start[warp];
    const int e = g_start[warp + 1];

    float4 acc0 = make_float4(0.f, 0.f, 0.f, 0.f);
    float4 acc1 = make_float4(0.f, 0.f, 0.f, 0.f);
    float  wsum = 0.f;

    for (int base = s; base < e; base += 32) {
        const int n = min(32, e - base);
        int   col = 0;
        float wv  = 0.f;
        if (lane < n) {
            col = g_scol[base + lane];
            wv  = __ldg(&g_wnode[col]);
        }
        for (int c = 0; c < n; ++c) {
            int   cc = __shfl_sync(0xffffffffu, col, c);
            float ww = __shfl_sync(0xffffffffu, wv,  c);
            const float4* src = (const float4*)(x + (long long)cc * DIM);
            float4 a = __ldg(src + lane);
            float4 b = __ldg(src + lane + 32);
            acc0.x = fmaf(ww, a.x, acc0.x);
            acc0.y = fmaf(ww, a.y, acc0.y);
            acc0.z = fmaf(ww, a.z, acc0.z);
            acc0.w = fmaf(ww, a.w, acc0.w);
            acc1.x = fmaf(ww, b.x, acc1.x);
            acc1.y = fmaf(ww, b.y, acc1.y);
            acc1.z = fmaf(ww, b.z, acc1.z);
            acc1.w = fmaf(ww, b.w, acc1.w);
            wsum += ww;
        }
    }

    float4* dst = (float4*)(out + (long long)warp * DIM);
    if (e > s) {
        float inv = 1.f / fmaxf(wsum, 1e-12f);
        acc0.x *= inv; acc0.y *= inv; acc0.z *= inv; acc0.w *= inv;
        acc1.x *= inv; acc1.y *= inv; acc1.z *= inv; acc1.w *= inv;
        dst[lane]      = acc0;
        dst[lane + 32] = acc1;
    } else {
        float4 z = make_float4(0.f, 0.f, 0.f, 0.f);
        dst[lane]      = z;
        dst[lane + 32] = z;
    }
}

// ---------------------------------------------------------------------------
extern "C" void kernel_launch(void* const* d_in, const int* in_sizes, int n_in,
                              void* d_out, int out_size) {
    const float* x   = (const float*)d_in[0];
    const void*  ei  = d_in[1];
    const float* W1  = (const float*)d_in[2];
    const float* b1  = (const float*)d_in[3];
    const float* W2  = (const float*)d_in[4];
    const float* b2  = (const float*)d_in[5];
    float*       out = (float*)d_out;

    static int smem_set = 0;
    if (!smem_set) {
        cudaFuncSetAttribute(node_weight_kernel,
                             cudaFuncAttributeMaxDynamicSharedMemorySize, NW_SMEM);
        smem_set = 1;
    }

    detect_kernel<<<1, 1>>>((const int*)ei);
    zero_cnt_kernel<<<(N_NODES + 255) / 256, 256>>>();
    prep_w1_kernel<<<(HID * DIM + 255) / 256, 256>>>(W1);
    count_kernel<<<(N_EDGES + NTHR - 1) / NTHR, NTHR>>>(ei);
    scan1_kernel<<<NB_SCAN, SCAN_B>>>();
    scan2_kernel<<<1, 32>>>();
    scan3_kernel<<<(N_NODES + 255) / 256, 256>>>();
    fill_kernel<<<(N_EDGES + NTHR - 1) / NTHR, NTHR>>>(ei);

    const int nw_blocks = (N_NODES + TM - 1) / TM;   // 782
    node_weight_kernel<<<nw_blocks, NTHR, NW_SMEM>>>(x, b1, W2, b2);

    const int agg_blocks = (N_NODES * 32 + NTHR - 1) / NTHR;  // 6250
    agg_kernel<<<agg_blocks, NTHR>>>(x, out);
}

// round 6
// speedup vs baseline: 1.2923x; 1.2923x over previous
#include <cuda_runtime.h>

#define N_NODES 50000
#define N_EDGES 800000
#define DIM     256
#define HID     128
#define TILE_N  32
#define NTHR    256
#define LDN     260
#define SCAN_B  1024
#define NB_SCAN ((N_NODES + SCAN_B - 1) / SCAN_B)   // 49

__device__ float g_wnode[N_NODES];
__device__ int   g_is64;
__device__ int   g_cnt[N_NODES];
__device__ int   g_incl[N_NODES];
__device__ int   g_btot[64];
__device__ int   g_start[N_NODES + 1];
__device__ int   g_cur[N_NODES + 1];
__device__ int   g_scol[N_EDGES];

// ---------------------------------------------------------------------------
__device__ __forceinline__ int load_idx(const void* ei, long long pos, bool is64) {
    int v = is64 ? (int)((const long long*)ei)[pos] : ((const int*)ei)[pos];
    return min(max(v, 0), N_NODES - 1);
}

// ---------------------------------------------------------------------------
__global__ void detect_kernel(const int* __restrict__ ei32) {
    int all_hi_zero = 1;
    #pragma unroll 8
    for (int i = 0; i < 512; ++i)
        if (ei32[2 * i + 1] != 0) { all_hi_zero = 0; break; }
    g_is64 = all_hi_zero;
}

__global__ void zero_cnt_kernel() {
    int i = blockIdx.x * blockDim.x + threadIdx.x;
    if (i < N_NODES) g_cnt[i] = 0;
}

// ---------------------------------------------------------------------------
// CSR build: count, scan, fill.
// ---------------------------------------------------------------------------
__global__ void count_kernel(const void* __restrict__ ei) {
    int e = blockIdx.x * blockDim.x + threadIdx.x;
    if (e >= N_EDGES) return;
    int row = load_idx(ei, e, g_is64 != 0);
    atomicAdd(&g_cnt[row], 1);
}

__global__ void scan1_kernel() {      // per-block inclusive scan, shuffle-based
    __shared__ int s_wt[32];
    const int t = threadIdx.x, b = blockIdx.x;
    const int lane = t & 31, wid = t >> 5;
    const int i = b * SCAN_B + t;
    int v = (i < N_NODES) ? g_cnt[i] : 0;
    int sv = v;
    #pragma unroll
    for (int off = 1; off < 32; off <<= 1) {
        int u = __shfl_up_sync(0xffffffffu, sv, off);
        if (lane >= off) sv += u;
    }
    if (lane == 31) s_wt[wid] = sv;
    __syncthreads();
    if (wid == 0) {
        int wv = s_wt[lane];
        #pragma unroll
        for (int off = 1; off < 32; off <<= 1) {
            int u = __shfl_up_sync(0xffffffffu, wv, off);
            if (lane >= off) wv += u;
        }
        s_wt[lane] = wv;
    }
    __syncthreads();
    int incl = sv + ((wid > 0) ? s_wt[wid - 1] : 0);
    if (i < N_NODES) g_incl[i] = incl;
    if (t == SCAN_B - 1) g_btot[b] = incl;
}

__global__ void scan2_kernel() {      // exclusive scan of 49 block totals
    if (threadIdx.x == 0) {
        int run = 0;
        #pragma unroll 1
        for (int b = 0; b < NB_SCAN; ++b) {
            int t = g_btot[b];
            g_btot[b] = run;
            run += t;
        }
    }
}

__global__ void scan3_kernel() {
    int i = blockIdx.x * blockDim.x + threadIdx.x;
    if (i >= N_NODES) return;
    int v = g_incl[i] + g_btot[i >> 10];
    g_start[i + 1] = v;
    g_cur[i + 1]   = v;
    if (i == 0) { g_start[0] = 0; g_cur[0] = 0; }
}

__global__ void fill_kernel(const void* __restrict__ ei) {
    int e = blockIdx.x * blockDim.x + threadIdx.x;
    if (e >= N_EDGES) return;
    bool is64 = (g_is64 != 0);
    int row = load_idx(ei, e, is64);
    int col = load_idx(ei, (long long)N_EDGES + e, is64);
    int pos = atomicAdd(&g_cur[row], 1);
    g_scol[pos] = col;
}

// ---------------------------------------------------------------------------
// Per-NODE attention weight: proven fp32 register-tiled GEMM (R4 version,
// 90us, at the FFMA-issue floor). The R5 mma.sync bf16 variant was SLOWER
// (~113us) -- sm_103a's fast tensor path is tcgen05, not register HMMA.
// ---------------------------------------------------------------------------
__global__ __launch_bounds__(NTHR, 4)
void node_weight_kernel(const float* __restrict__ x,
                        const float* __restrict__ W1,
                        const float* __restrict__ b1,
                        const float* __restrict__ W2,
                        const float* __restrict__ b2)
{
    __shared__ float s_x[TILE_N][LDN];
    __shared__ float s_w[TILE_N];

    const int tid  = threadIdx.x;
    const int eg   = tid >> 5;
    const int jg   = tid & 31;
    const int base = blockIdx.x * TILE_N;

    #pragma unroll
    for (int it = 0; it < (TILE_N * (DIM / 4)) / NTHR; ++it) {
        int f = it * NTHR + tid;
        int e = f >> 6;
        int q = f & 63;
        int node = min(base + e, N_NODES - 1);
        float4 v = __ldg(((const float4*)(x + (long long)node * DIM)) + q);
        *(float4*)&s_x[e][q * 4] = v;
    }
    __syncthreads();

    float acc[4][4];
    #pragma unroll
    for (int e = 0; e < 4; ++e)
        #pragma unroll
        for (int j = 0; j < 4; ++j) acc[e][j] = 0.f;

    const float4* W1v = (const float4*)W1;
    #pragma unroll 4
    for (int k4 = 0; k4 < DIM / 4; ++k4) {
        const int k = k4 * 4;
        float w1r[4][4];
        #pragma unroll
        for (int kk = 0; kk < 4; ++kk)
            *(float4*)w1r[kk] = __ldg(&W1v[(k + kk) * (HID / 4) + jg]);
        #pragma unroll
        for (int e = 0; e < 4; ++e) {
            float4 nv = *(const float4*)&s_x[eg * 4 + e][k];
            float nvv[4] = {nv.x, nv.y, nv.z, nv.w};
            #pragma unroll
            for (int kk = 0; kk < 4; ++kk)
                #pragma unroll
                for (int j = 0; j < 4; ++j)
                    acc[e][j] = fmaf(nvv[kk], w1r[kk][j], acc[e][j]);
        }
    }

    float4 b1v = __ldg(((const float4*)b1) + jg);
    float4 w2v = __ldg(((const float4*)W2) + jg);
    float b1a[4] = {b1v.x, b1v.y, b1v.z, b1v.w};
    float w2a[4] = {w2v.x, w2v.y, w2v.z, w2v.w};

    float psum[4];
    #pragma unroll
    for (int e = 0; e < 4; ++e) {
        float s = 0.f;
        #pragma unroll
        for (int j = 0; j < 4; ++j) {
            float h = fmaxf(acc[e][j] + b1a[j], 0.f);
            s = fmaf(h, w2a[j], s);
        }
        psum[e] = s;
    }
    #pragma unroll
    for (int off = 16; off > 0; off >>= 1)
        #pragma unroll
        for (int e = 0; e < 4; ++e)
            psum[e] += __shfl_xor_sync(0xffffffffu, psum[e], off);

    float b2v = __ldg(b2);
    if (jg < 4) {
        float logit = psum[jg] + b2v;
        s_w[eg * 4 + jg] = 1.f / (1.f + expf(-logit));
    }
    __syncthreads();

    if (tid < TILE_N) {
        int node = base + tid;
        if (node < N_NODES) g_wnode[node] = s_w[tid];
    }
}

// ---------------------------------------------------------------------------
// Aggregation: one warp per destination node (R4 winner, at L2 gather floor).
// ---------------------------------------------------------------------------
__global__ __launch_bounds__(NTHR, 8)
void agg_kernel(const float* __restrict__ x, float* __restrict__ out)
{
    const int warp = (blockIdx.x * NTHR + threadIdx.x) >> 5;
    const int lane = threadIdx.x & 31;
    if (warp >= N_NODES) return;

    const int s = g_start[warp];
    const int e = g_start[warp + 1];

    float4 acc0 = make_float4(0.f, 0.f, 0.f, 0.f);
    float4 acc1 = make_float4(0.f, 0.f, 0.f, 0.f);
    float  wsum = 0.f;

    for (int base = s; base < e; base += 32) {
        const int n = min(32, e - base);
        int   col = 0;
        float wv  = 0.f;
        if (lane < n) {
            col = g_scol[base + lane];
            wv  = __ldg(&g_wnode[col]);
        }
        for (int c = 0; c < n; ++c) {
            int   cc = __shfl_sync(0xffffffffu, col, c);
            float ww = __shfl_sync(0xffffffffu, wv,  c);
            const float4* src = (const float4*)(x + (long long)cc * DIM);
            float4 a = __ldg(src + lane);
            float4 b = __ldg(src + lane + 32);
            acc0.x = fmaf(ww, a.x, acc0.x);
            acc0.y = fmaf(ww, a.y, acc0.y);
            acc0.z = fmaf(ww, a.z, acc0.z);
            acc0.w = fmaf(ww, a.w, acc0.w);
            acc1.x = fmaf(ww, b.x, acc1.x);
            acc1.y = fmaf(ww, b.y, acc1.y);
            acc1.z = fmaf(ww, b.z, acc1.z);
            acc1.w = fmaf(ww, b.w, acc1.w);
            wsum += ww;
        }
    }

    float4* dst = (float4*)(out + (long long)warp * DIM);
    if (e > s) {
        float inv = 1.f / fmaxf(wsum, 1e-12f);
        acc0.x *= inv; acc0.y *= inv; acc0.z *= inv; acc0.w *= inv;
        acc1.x *= inv; acc1.y *= inv; acc1.z *= inv; acc1.w *= inv;
        dst[lane]      = acc0;
        dst[lane + 32] = acc1;
    } else {
        float4 z = make_float4(0.f, 0.f, 0.f, 0.f);
        dst[lane]      = z;
        dst[lane + 32] = z;
    }
}

// ---------------------------------------------------------------------------
// Launch: fork the CSR build onto a side stream so it overlaps with the
// FFMA-bound node_weight GEMM; join before agg. Streams/events are created
// once during the (uncaptured) correctness call and reused inside capture.
// ---------------------------------------------------------------------------
extern "C" void kernel_launch(void* const* d_in, const int* in_sizes, int n_in,
                              void* d_out, int out_size) {
    const float* x   = (const float*)d_in[0];
    const void*  ei  = d_in[1];
    const float* W1  = (const float*)d_in[2];
    const float* b1  = (const float*)d_in[3];
    const float* W2  = (const float*)d_in[4];
    const float* b2  = (const float*)d_in[5];
    float*       out = (float*)d_out;

    static cudaStream_t s_side = nullptr;
    static cudaEvent_t  ev_fork = nullptr, ev_join = nullptr;
    if (!s_side) {
        cudaStreamCreateWithFlags(&s_side, cudaStreamNonBlocking);
        cudaEventCreateWithFlags(&ev_fork, cudaEventDisableTiming);
        cudaEventCreateWithFlags(&ev_join, cudaEventDisableTiming);
    }

    // fork: side stream depends on stream-0 tip
    cudaEventRecord(ev_fork, 0);
    cudaStreamWaitEvent(s_side, ev_fork, 0);

    // side stream: CSR build chain (~25us, memory/atomic pipes)
    detect_kernel<<<1, 1, 0, s_side>>>((const int*)ei);
    zero_cnt_kernel<<<(N_NODES + 255) / 256, 256, 0, s_side>>>();
    count_kernel<<<(N_EDGES + NTHR - 1) / NTHR, NTHR, 0, s_side>>>(ei);
    scan1_kernel<<<NB_SCAN, SCAN_B, 0, s_side>>>();
    scan2_kernel<<<1, 32, 0, s_side>>>();
    scan3_kernel<<<(N_NODES + 255) / 256, 256, 0, s_side>>>();
    fill_kernel<<<(N_EDGES + NTHR - 1) / NTHR, NTHR, 0, s_side>>>(ei);
    cudaEventRecord(ev_join, s_side);

    // main stream: node weights (FFMA-bound, ~90us) runs concurrently
    const int nw_blocks = (N_NODES + TILE_N - 1) / TILE_N;
    node_weight_kernel<<<nw_blocks, NTHR>>>(x, W1, b1, W2, b2);

    // join, then aggregate
    cudaStreamWaitEvent(0, ev_join, 0);
    const int agg_blocks = (N_NODES * 32 + NTHR - 1) / NTHR;  // 6250
    agg_kernel<<<agg_blocks, NTHR>>>(x, out);
}

// round 8
// speedup vs baseline: 1.3237x; 1.0243x over previous
#include <cuda_runtime.h>
#include <cuda_fp16.h>

#define N_NODES 50000
#define N_EDGES 800000
#define DIM     256
#define HID     128
#define TILE_N  32
#define NTHR    256
#define LDN     260
#define SCAN_B  1024
#define NB_SCAN ((N_NODES + SCAN_B - 1) / SCAN_B)   // 49

__device__ float g_wnode[N_NODES];
__device__ int   g_is64;
__device__ int   g_cnt[N_NODES];
__device__ int   g_incl[N_NODES];
__device__ int   g_btot[64];
__device__ int   g_start[N_NODES + 1];
__device__ int   g_cur[N_NODES + 1];
__device__ int   g_scol[N_EDGES];
__device__ __align__(16) __half g_xh[N_NODES * DIM];   // fp16 mirror of x (25.6MB)

// ---------------------------------------------------------------------------
__device__ __forceinline__ int load_idx(const void* ei, long long pos, bool is64) {
    int v = is64 ? (int)((const long long*)ei)[pos] : ((const int*)ei)[pos];
    return min(max(v, 0), N_NODES - 1);
}

// ---------------------------------------------------------------------------
__global__ void detect_kernel(const int* __restrict__ ei32) {
    int all_hi_zero = 1;
    #pragma unroll 8
    for (int i = 0; i < 512; ++i)
        if (ei32[2 * i + 1] != 0) { all_hi_zero = 0; break; }
    g_is64 = all_hi_zero;
}

__global__ void zero_cnt_kernel() {
    int i = blockIdx.x * blockDim.x + threadIdx.x;
    if (i < N_NODES) g_cnt[i] = 0;
}

// x -> fp16 mirror (weights in agg stay fp32; only the gathered features are
// quantized, a convex combination -> rms rel err ~2.8e-4, 3.5x under budget).
__global__ void convert_x_kernel(const float4* __restrict__ x4) {
    const int total = N_NODES * (DIM / 4);
    int i = blockIdx.x * blockDim.x + threadIdx.x;
    if (i >= total) return;
    float4 v = __ldg(&x4[i]);
    __half2 a = __floats2half2_rn(v.x, v.y);
    __half2 b = __floats2half2_rn(v.z, v.w);
    __half2* dst = (__half2*)g_xh;
    dst[2 * i]     = a;
    dst[2 * i + 1] = b;
}

// ---------------------------------------------------------------------------
// CSR build
// ---------------------------------------------------------------------------
__global__ void count_kernel(const void* __restrict__ ei) {
    int e = blockIdx.x * blockDim.x + threadIdx.x;
    if (e >= N_EDGES) return;
    int row = load_idx(ei, e, g_is64 != 0);
    atomicAdd(&g_cnt[row], 1);
}

__global__ void scan1_kernel() {
    __shared__ int s_wt[32];
    const int t = threadIdx.x, b = blockIdx.x;
    const int lane = t & 31, wid = t >> 5;
    const int i = b * SCAN_B + t;
    int sv = (i < N_NODES) ? g_cnt[i] : 0;
    #pragma unroll
    for (int off = 1; off < 32; off <<= 1) {
        int u = __shfl_up_sync(0xffffffffu, sv, off);
        if (lane >= off) sv += u;
    }
    if (lane == 31) s_wt[wid] = sv;
    __syncthreads();
    if (wid == 0) {
        int wv = s_wt[lane];
        #pragma unroll
        for (int off = 1; off < 32; off <<= 1) {
            int u = __shfl_up_sync(0xffffffffu, wv, off);
            if (lane >= off) wv += u;
        }
        s_wt[lane] = wv;
    }
    __syncthreads();
    int incl = sv + ((wid > 0) ? s_wt[wid - 1] : 0);
    if (i < N_NODES) g_incl[i] = incl;
    if (t == SCAN_B - 1) g_btot[b] = incl;
}

__global__ void scan2_kernel() {
    if (threadIdx.x == 0) {
        int run = 0;
        #pragma unroll 1
        for (int b = 0; b < NB_SCAN; ++b) {
            int t = g_btot[b];
            g_btot[b] = run;
            run += t;
        }
    }
}

__global__ void scan3_kernel() {
    int i = blockIdx.x * blockDim.x + threadIdx.x;
    if (i >= N_NODES) return;
    int v = g_incl[i] + g_btot[i >> 10];
    g_start[i + 1] = v;
    g_cur[i + 1]   = v;
    if (i == 0) { g_start[0] = 0; g_cur[0] = 0; }
}

__global__ void fill_kernel(const void* __restrict__ ei) {
    int e = blockIdx.x * blockDim.x + threadIdx.x;
    if (e >= N_EDGES) return;
    bool is64 = (g_is64 != 0);
    int row = load_idx(ei, e, is64);
    int col = load_idx(ei, (long long)N_EDGES + e, is64);
    int pos = atomicAdd(&g_cur[row], 1);
    g_scol[pos] = col;
}

// ---------------------------------------------------------------------------
// Per-NODE attention weight: proven fp32 register-tiled GEMM (FFMA floor).
// tcgen05 is unavailable in this toolchain (ptxas targets plain sm_103) and
// register-path mma.sync measured SLOWER than FFMA in R5 -- fp32 stays.
// ---------------------------------------------------------------------------
__global__ __launch_bounds__(NTHR, 4)
void node_weight_kernel(const float* __restrict__ x,
                        const float* __restrict__ W1,
                        const float* __restrict__ b1,
                        const float* __restrict__ W2,
                        const float* __restrict__ b2)
{
    __shared__ float s_x[TILE_N][LDN];
    __shared__ float s_w[TILE_N];

    const int tid  = threadIdx.x;
    const int eg   = tid >> 5;
    const int jg   = tid & 31;
    const int base = blockIdx.x * TILE_N;

    #pragma unroll
    for (int it = 0; it < (TILE_N * (DIM / 4)) / NTHR; ++it) {
        int f = it * NTHR + tid;
        int e = f >> 6;
        int q = f & 63;
        int node = min(base + e, N_NODES - 1);
        float4 v = __ldg(((const float4*)(x + (long long)node * DIM)) + q);
        *(float4*)&s_x[e][q * 4] = v;
    }
    __syncthreads();

    float acc[4][4];
    #pragma unroll
    for (int e = 0; e < 4; ++e)
        #pragma unroll
        for (int j = 0; j < 4; ++j) acc[e][j] = 0.f;

    const float4* W1v = (const float4*)W1;
    #pragma unroll 4
    for (int k4 = 0; k4 < DIM / 4; ++k4) {
        const int k = k4 * 4;
        float w1r[4][4];
        #pragma unroll
        for (int kk = 0; kk < 4; ++kk)
            *(float4*)w1r[kk] = __ldg(&W1v[(k + kk) * (HID / 4) + jg]);
        #pragma unroll
        for (int e = 0; e < 4; ++e) {
            float4 nv = *(const float4*)&s_x[eg * 4 + e][k];
            float nvv[4] = {nv.x, nv.y, nv.z, nv.w};
            #pragma unroll
            for (int kk = 0; kk < 4; ++kk)
                #pragma unroll
                for (int j = 0; j < 4; ++j)
                    acc[e][j] = fmaf(nvv[kk], w1r[kk][j], acc[e][j]);
        }
    }

    float4 b1v = __ldg(((const float4*)b1) + jg);
    float4 w2v = __ldg(((const float4*)W2) + jg);
    float b1a[4] = {b1v.x, b1v.y, b1v.z, b1v.w};
    float w2a[4] = {w2v.x, w2v.y, w2v.z, w2v.w};

    float psum[4];
    #pragma unroll
    for (int e = 0; e < 4; ++e) {
        float s = 0.f;
        #pragma unroll
        for (int j = 0; j < 4; ++j) {
            float h = fmaxf(acc[e][j] + b1a[j], 0.f);
            s = fmaf(h, w2a[j], s);
        }
        psum[e] = s;
    }
    #pragma unroll
    for (int off = 16; off > 0; off >>= 1)
        #pragma unroll
        for (int e = 0; e < 4; ++e)
            psum[e] += __shfl_xor_sync(0xffffffffu, psum[e], off);

    float b2v = __ldg(b2);
    if (jg < 4) {
        float logit = psum[jg] + b2v;
        s_w[eg * 4 + jg] = 1.f / (1.f + expf(-logit));
    }
    __syncthreads();

    if (tid < TILE_N) {
        int node = base + tid;
        if (node < N_NODES) g_wnode[node] = s_w[tid];
    }
}

// ---------------------------------------------------------------------------
// Aggregation: one warp per destination node, fp16 gather (512B/edge),
// fp32 weights + fp32 accumulation, fused normalize + store.
// ---------------------------------------------------------------------------
__global__ __launch_bounds__(NTHR, 8)
void agg_kernel(float* __restrict__ out)
{
    const int warp = (blockIdx.x * NTHR + threadIdx.x) >> 5;
    const int lane = threadIdx.x & 31;
    if (warp >= N_NODES) return;

    const int s = g_start[warp];
    const int e = g_start[warp + 1];

    float acc[8] = {0.f, 0.f, 0.f, 0.f, 0.f, 0.f, 0.f, 0.f};
    float wsum = 0.f;

    for (int base = s; base < e; base += 32) {
        const int n = min(32, e - base);
        int   col = 0;
        float wv  = 0.f;
        if (lane < n) {
            col = g_scol[base + lane];
            wv  = __ldg(&g_wnode[col]);
        }
        for (int c = 0; c < n; ++c) {
            int   cc = __shfl_sync(0xffffffffu, col, c);
            float ww = __shfl_sync(0xffffffffu, wv,  c);
            const uint4* src = (const uint4*)(g_xh + (long long)cc * DIM);
            uint4 p = __ldg(src + lane);          // 8 halfs
            float2 f0 = __half22float2(*(const __half2*)&p.x);
            float2 f1 = __half22float2(*(const __half2*)&p.y);
            float2 f2 = __half22float2(*(const __half2*)&p.z);
            float2 f3 = __half22float2(*(const __half2*)&p.w);
            acc[0] = fmaf(ww, f0.x, acc[0]);
            acc[1] = fmaf(ww, f0.y, acc[1]);
            acc[2] = fmaf(ww, f1.x, acc[2]);
            acc[3] = fmaf(ww, f1.y, acc[3]);
            acc[4] = fmaf(ww, f2.x, acc[4]);
            acc[5] = fmaf(ww, f2.y, acc[5]);
            acc[6] = fmaf(ww, f3.x, acc[6]);
            acc[7] = fmaf(ww, f3.y, acc[7]);
            wsum += ww;
        }
    }

    float4* dst = (float4*)(out + (long long)warp * DIM) + lane * 2;
    if (e > s) {
        float inv = 1.f / fmaxf(wsum, 1e-12f);
        dst[0] = make_float4(acc[0] * inv, acc[1] * inv, acc[2] * inv, acc[3] * inv);
        dst[1] = make_float4(acc[4] * inv, acc[5] * inv, acc[6] * inv, acc[7] * inv);
    } else {
        float4 z = make_float4(0.f, 0.f, 0.f, 0.f);
        dst[0] = z;
        dst[1] = z;
    }
}

// ---------------------------------------------------------------------------
// Launch: side stream = x->fp16 convert + CSR build (~35us) overlapped with
// the FFMA-bound node_weight GEMM (~90us) on the main stream; join, then agg.
// ---------------------------------------------------------------------------
extern "C" void kernel_launch(void* const* d_in, const int* in_sizes, int n_in,
                              void* d_out, int out_size) {
    const float* x   = (const float*)d_in[0];
    const void*  ei  = d_in[1];
    const float* W1  = (const float*)d_in[2];
    const float* b1  = (const float*)d_in[3];
    const float* W2  = (const float*)d_in[4];
    const float* b2  = (const float*)d_in[5];
    float*       out = (float*)d_out;

    static cudaStream_t s_side = nullptr;
    static cudaEvent_t  ev_fork = nullptr, ev_join = nullptr;
    if (!s_side) {
        cudaStreamCreateWithFlags(&s_side, cudaStreamNonBlocking);
        cudaEventCreateWithFlags(&ev_fork, cudaEventDisableTiming);
        cudaEventCreateWithFlags(&ev_join, cudaEventDisableTiming);
    }

    cudaEventRecord(ev_fork, 0);
    cudaStreamWaitEvent(s_side, ev_fork, 0);

    // side stream: fp16 mirror of x, then CSR build
    const int total4 = N_NODES * (DIM / 4);
    convert_x_kernel<<<(total4 + 255) / 256, 256, 0, s_side>>>((const float4*)x);
    detect_kernel<<<1, 1, 0, s_side>>>((const int*)ei);
    zero_cnt_kernel<<<(N_NODES + 255) / 256, 256, 0, s_side>>>();
    count_kernel<<<(N_EDGES + NTHR - 1) / NTHR, NTHR, 0, s_side>>>(ei);
    scan1_kernel<<<NB_SCAN, SCAN_B, 0, s_side>>>();
    scan2_kernel<<<1, 32, 0, s_side>>>();
    scan3_kernel<<<(N_NODES + 255) / 256, 256, 0, s_side>>>();
    fill_kernel<<<(N_EDGES + NTHR - 1) / NTHR, NTHR, 0, s_side>>>(ei);
    cudaEventRecord(ev_join, s_side);

    // main stream: node weights (FFMA-bound) runs concurrently
    const int nw_blocks = (N_NODES + TILE_N - 1) / TILE_N;
    node_weight_kernel<<<nw_blocks, NTHR>>>(x, W1, b1, W2, b2);

    cudaStreamWaitEvent(0, ev_join, 0);
    const int agg_blocks = (N_NODES * 32 + NTHR - 1) / NTHR;  // 6250
    agg_kernel<<<agg_blocks, NTHR>>>(out);
}

// round 9
// speedup vs baseline: 1.3539x; 1.0228x over previous
#include <cuda_runtime.h>
#include <cuda_fp16.h>

#define N_NODES 50000
#define N_EDGES 800000
#define DIM     256
#define HID     128
#define TILE_N  32
#define NTHR    256
#define LDN     260
#define SCAN_B  1024
#define NB_SCAN ((N_NODES + SCAN_B - 1) / SCAN_B)   // 49

__device__ float g_wnode[N_NODES];
__device__ int   g_is64;
__device__ int   g_cnt[N_NODES];
__device__ int   g_incl[N_NODES];
__device__ int   g_btot[64];
__device__ int   g_start[N_NODES + 1];
__device__ int   g_cur[N_NODES + 1];
__device__ int   g_scol[N_EDGES];
__device__ __align__(16) __half g_xh[N_NODES * DIM];   // fp16 mirror of x (25.6MB)

// ---------------------------------------------------------------------------
// packed f32x2 helpers (FFMA2 -- 2 fp32 MACs per FMA-pipe slot)
// ---------------------------------------------------------------------------
__device__ __forceinline__ void ffma2(unsigned long long& c,
                                      unsigned long long a,
                                      unsigned long long b) {
    asm("fma.rn.f32x2 %0, %1, %2, %0;" : "+l"(c) : "l"(a), "l"(b));
}
__device__ __forceinline__ unsigned long long dup2(float v) {
    unsigned long long r;
    unsigned u = __float_as_uint(v);
    asm("mov.b64 %0, {%1, %1};" : "=l"(r) : "r"(u));
    return r;
}
__device__ __forceinline__ float2 unpack2(unsigned long long v) {
    unsigned lo, hi;
    asm("mov.b64 {%0, %1}, %2;" : "=r"(lo), "=r"(hi) : "l"(v));
    return make_float2(__uint_as_float(lo), __uint_as_float(hi));
}

// ---------------------------------------------------------------------------
__device__ __forceinline__ int load_idx(const void* ei, long long pos, bool is64) {
    int v = is64 ? (int)((const long long*)ei)[pos] : ((const int*)ei)[pos];
    return min(max(v, 0), N_NODES - 1);
}

// ---------------------------------------------------------------------------
__global__ void detect_kernel(const int* __restrict__ ei32) {
    int all_hi_zero = 1;
    #pragma unroll 8
    for (int i = 0; i < 512; ++i)
        if (ei32[2 * i + 1] != 0) { all_hi_zero = 0; break; }
    g_is64 = all_hi_zero;
}

__global__ void zero_cnt_kernel() {
    int i = blockIdx.x * blockDim.x + threadIdx.x;
    if (i < N_NODES) g_cnt[i] = 0;
}

// x -> fp16 mirror (agg gathers fp16; weights stay fp32)
__global__ void convert_x_kernel(const float4* __restrict__ x4) {
    const int total = N_NODES * (DIM / 4);
    int i = blockIdx.x * blockDim.x + threadIdx.x;
    if (i >= total) return;
    float4 v = __ldg(&x4[i]);
    __half2 a = __floats2half2_rn(v.x, v.y);
    __half2 b = __floats2half2_rn(v.z, v.w);
    __half2* dst = (__half2*)g_xh;
    dst[2 * i]     = a;
    dst[2 * i + 1] = b;
}

// ---------------------------------------------------------------------------
// CSR build
// ---------------------------------------------------------------------------
__global__ void count_kernel(const void* __restrict__ ei) {
    int e = blockIdx.x * blockDim.x + threadIdx.x;
    if (e >= N_EDGES) return;
    int row = load_idx(ei, e, g_is64 != 0);
    atomicAdd(&g_cnt[row], 1);
}

__global__ void scan1_kernel() {
    __shared__ int s_wt[32];
    const int t = threadIdx.x, b = blockIdx.x;
    const int lane = t & 31, wid = t >> 5;
    const int i = b * SCAN_B + t;
    int sv = (i < N_NODES) ? g_cnt[i] : 0;
    #pragma unroll
    for (int off = 1; off < 32; off <<= 1) {
        int u = __shfl_up_sync(0xffffffffu, sv, off);
        if (lane >= off) sv += u;
    }
    if (lane == 31) s_wt[wid] = sv;
    __syncthreads();
    if (wid == 0) {
        int wv = s_wt[lane];
        #pragma unroll
        for (int off = 1; off < 32; off <<= 1) {
            int u = __shfl_up_sync(0xffffffffu, wv, off);
            if (lane >= off) wv += u;
        }
        s_wt[lane] = wv;
    }
    __syncthreads();
    int incl = sv + ((wid > 0) ? s_wt[wid - 1] : 0);
    if (i < N_NODES) g_incl[i] = incl;
    if (t == SCAN_B - 1) g_btot[b] = incl;
}

__global__ void scan2_kernel() {
    if (threadIdx.x == 0) {
        int run = 0;
        #pragma unroll 1
        for (int b = 0; b < NB_SCAN; ++b) {
            int t = g_btot[b];
            g_btot[b] = run;
            run += t;
        }
    }
}

__global__ void scan3_kernel() {
    int i = blockIdx.x * blockDim.x + threadIdx.x;
    if (i >= N_NODES) return;
    int v = g_incl[i] + g_btot[i >> 10];
    g_start[i + 1] = v;
    g_cur[i + 1]   = v;
    if (i == 0) { g_start[0] = 0; g_cur[0] = 0; }
}

__global__ void fill_kernel(const void* __restrict__ ei) {
    int e = blockIdx.x * blockDim.x + threadIdx.x;
    if (e >= N_EDGES) return;
    bool is64 = (g_is64 != 0);
    int row = load_idx(ei, e, is64);
    int col = load_idx(ei, (long long)N_EDGES + e, is64);
    int pos = atomicAdd(&g_cur[row], 1);
    g_scol[pos] = col;
}

// ---------------------------------------------------------------------------
// Per-NODE attention weight, now with packed fma.rn.f32x2 (FFMA2):
// halves the FMA-pipe slots (the binding pipe at rt 2/SMSP) at full fp32
// precision. acc packed over j-pairs; W1 float4 loads reinterpreted as
// ulonglong2 (free pairing); x scalar dup'd via mov.b64 (alu pipe, hidden).
// ---------------------------------------------------------------------------
__global__ __launch_bounds__(NTHR, 4)
void node_weight_kernel(const float* __restrict__ x,
                        const float* __restrict__ W1,
                        const float* __restrict__ b1,
                        const float* __restrict__ W2,
                        const float* __restrict__ b2)
{
    __shared__ float s_x[TILE_N][LDN];
    __shared__ float s_w[TILE_N];

    const int tid  = threadIdx.x;
    const int eg   = tid >> 5;
    const int jg   = tid & 31;
    const int base = blockIdx.x * TILE_N;

    #pragma unroll
    for (int it = 0; it < (TILE_N * (DIM / 4)) / NTHR; ++it) {
        int f = it * NTHR + tid;
        int e = f >> 6;
        int q = f & 63;
        int node = min(base + e, N_NODES - 1);
        float4 v = __ldg(((const float4*)(x + (long long)node * DIM)) + q);
        *(float4*)&s_x[e][q * 4] = v;
    }
    __syncthreads();

    unsigned long long acc2[4][2];
    #pragma unroll
    for (int e = 0; e < 4; ++e) { acc2[e][0] = 0ull; acc2[e][1] = 0ull; }

    const float4* W1v = (const float4*)W1;   // row k: W1v[k*(HID/4) + jg]
    #pragma unroll 4
    for (int k4 = 0; k4 < DIM / 4; ++k4) {
        const int k = k4 * 4;
        ulonglong2 w1p[4];
        #pragma unroll
        for (int kk = 0; kk < 4; ++kk)
            w1p[kk] = __ldg((const ulonglong2*)&W1v[(k + kk) * (HID / 4) + jg]);
        #pragma unroll
        for (int e = 0; e < 4; ++e) {
            float4 nv = *(const float4*)&s_x[eg * 4 + e][k];
            unsigned long long d0 = dup2(nv.x);
            unsigned long long d1 = dup2(nv.y);
            unsigned long long d2 = dup2(nv.z);
            unsigned long long d3 = dup2(nv.w);
            ffma2(acc2[e][0], d0, w1p[0].x);
            ffma2(acc2[e][1], d0, w1p[0].y);
            ffma2(acc2[e][0], d1, w1p[1].x);
            ffma2(acc2[e][1], d1, w1p[1].y);
            ffma2(acc2[e][0], d2, w1p[2].x);
            ffma2(acc2[e][1], d2, w1p[2].y);
            ffma2(acc2[e][0], d3, w1p[3].x);
            ffma2(acc2[e][1], d3, w1p[3].y);
        }
    }

    // --- epilogue: relu(acc + b1) . W2, warp shuffle reduce, sigmoid ---
    float4 b1v = __ldg(((const float4*)b1) + jg);
    float4 w2v = __ldg(((const float4*)W2) + jg);
    float b1a[4] = {b1v.x, b1v.y, b1v.z, b1v.w};
    float w2a[4] = {w2v.x, w2v.y, w2v.z, w2v.w};

    float psum[4];
    #pragma unroll
    for (int e = 0; e < 4; ++e) {
        float2 p01 = unpack2(acc2[e][0]);
        float2 p23 = unpack2(acc2[e][1]);
        float a[4] = {p01.x, p01.y, p23.x, p23.y};
        float s = 0.f;
        #pragma unroll
        for (int j = 0; j < 4; ++j) {
            float h = fmaxf(a[j] + b1a[j], 0.f);
            s = fmaf(h, w2a[j], s);
        }
        psum[e] = s;
    }
    #pragma unroll
    for (int off = 16; off > 0; off >>= 1)
        #pragma unroll
        for (int e = 0; e < 4; ++e)
            psum[e] += __shfl_xor_sync(0xffffffffu, psum[e], off);

    float b2v = __ldg(b2);
    if (jg < 4) {
        float logit = psum[jg] + b2v;
        s_w[eg * 4 + jg] = 1.f / (1.f + expf(-logit));
    }
    __syncthreads();

    if (tid < TILE_N) {
        int node = base + tid;
        if (node < N_NODES) g_wnode[node] = s_w[tid];
    }
}

// ---------------------------------------------------------------------------
// Aggregation: one warp per destination node, fp16 gather, fp32 accumulate.
// ---------------------------------------------------------------------------
__global__ __launch_bounds__(NTHR, 8)
void agg_kernel(float* __restrict__ out)
{
    const int warp = (blockIdx.x * NTHR + threadIdx.x) >> 5;
    const int lane = threadIdx.x & 31;
    if (warp >= N_NODES) return;

    const int s = g_start[warp];
    const int e = g_start[warp + 1];

    float acc[8] = {0.f, 0.f, 0.f, 0.f, 0.f, 0.f, 0.f, 0.f};
    float wsum = 0.f;

    for (int base = s; base < e; base += 32) {
        const int n = min(32, e - base);
        int   col = 0;
        float wv  = 0.f;
        if (lane < n) {
            col = g_scol[base + lane];
            wv  = __ldg(&g_wnode[col]);
        }
        for (int c = 0; c < n; ++c) {
            int   cc = __shfl_sync(0xffffffffu, col, c);
            float ww = __shfl_sync(0xffffffffu, wv,  c);
            const uint4* src = (const uint4*)(g_xh + (long long)cc * DIM);
            uint4 p = __ldg(src + lane);          // 8 halfs
            float2 f0 = __half22float2(*(const __half2*)&p.x);
            float2 f1 = __half22float2(*(const __half2*)&p.y);
            float2 f2 = __half22float2(*(const __half2*)&p.z);
            float2 f3 = __half22float2(*(const __half2*)&p.w);
            acc[0] = fmaf(ww, f0.x, acc[0]);
            acc[1] = fmaf(ww, f0.y, acc[1]);
            acc[2] = fmaf(ww, f1.x, acc[2]);
            acc[3] = fmaf(ww, f1.y, acc[3]);
            acc[4] = fmaf(ww, f2.x, acc[4]);
            acc[5] = fmaf(ww, f2.y, acc[5]);
            acc[6] = fmaf(ww, f3.x, acc[6]);
            acc[7] = fmaf(ww, f3.y, acc[7]);
            wsum += ww;
        }
    }

    float4* dst = (float4*)(out + (long long)warp * DIM) + lane * 2;
    if (e > s) {
        float inv = 1.f / fmaxf(wsum, 1e-12f);
        dst[0] = make_float4(acc[0] * inv, acc[1] * inv, acc[2] * inv, acc[3] * inv);
        dst[1] = make_float4(acc[4] * inv, acc[5] * inv, acc[6] * inv, acc[7] * inv);
    } else {
        float4 z = make_float4(0.f, 0.f, 0.f, 0.f);
        dst[0] = z;
        dst[1] = z;
    }
}

// ---------------------------------------------------------------------------
extern "C" void kernel_launch(void* const* d_in, const int* in_sizes, int n_in,
                              void* d_out, int out_size) {
    const float* x   = (const float*)d_in[0];
    const void*  ei  = d_in[1];
    const float* W1  = (const float*)d_in[2];
    const float* b1  = (const float*)d_in[3];
    const float* W2  = (const float*)d_in[4];
    const float* b2  = (const float*)d_in[5];
    float*       out = (float*)d_out;

    static cudaStream_t s_side = nullptr;
    static cudaEvent_t  ev_fork = nullptr, ev_join = nullptr;
    if (!s_side) {
        cudaStreamCreateWithFlags(&s_side, cudaStreamNonBlocking);
        cudaEventCreateWithFlags(&ev_fork, cudaEventDisableTiming);
        cudaEventCreateWithFlags(&ev_join, cudaEventDisableTiming);
    }

    cudaEventRecord(ev_fork, 0);
    cudaStreamWaitEvent(s_side, ev_fork, 0);

    // side stream: fp16 mirror of x, then CSR build
    const int total4 = N_NODES * (DIM / 4);
    convert_x_kernel<<<(total4 + 255) / 256, 256, 0, s_side>>>((const float4*)x);
    detect_kernel<<<1, 1, 0, s_side>>>((const int*)ei);
    zero_cnt_kernel<<<(N_NODES + 255) / 256, 256, 0, s_side>>>();
    count_kernel<<<(N_EDGES + NTHR - 1) / NTHR, NTHR, 0, s_side>>>(ei);
    scan1_kernel<<<NB_SCAN, SCAN_B, 0, s_side>>>();
    scan2_kernel<<<1, 32, 0, s_side>>>();
    scan3_kernel<<<(N_NODES + 255) / 256, 256, 0, s_side>>>();
    fill_kernel<<<(N_EDGES + NTHR - 1) / NTHR, NTHR, 0, s_side>>>(ei);
    cudaEventRecord(ev_join, s_side);

    // main stream: node weights (FFMA2-bound now) runs concurrently
    const int nw_blocks = (N_NODES + TILE_N - 1) / TILE_N;
    node_weight_kernel<<<nw_blocks, NTHR>>>(x, W1, b1, W2, b2);

    cudaStreamWaitEvent(0, ev_join, 0);
    const int agg_blocks = (N_NODES * 32 + NTHR - 1) / NTHR;  // 6250
    agg_kernel<<<agg_blocks, NTHR>>>(out);
}

// round 10
// speedup vs baseline: 1.5071x; 1.1131x over previous
#include <cuda_runtime.h>
#include <cuda_fp16.h>

#define N_NODES 50000
#define N_EDGES 800000
#define DIM     256
#define HID     128
#define NTHR    256
#define SCAN_B  1024
#define NB_SCAN ((N_NODES + SCAN_B - 1) / SCAN_B)   // 49

#define TM      64                 // nodes per block in node_weight
#define LDK     264                // padded fp16 row stride (256 + 8)
#define NW_SMEM (TM * LDK * 2)     // one fp16 plane: 33792 bytes

__device__ float g_wnode[N_NODES];
__device__ int   g_is64;
__device__ int   g_cnt[N_NODES];
__device__ int   g_incl[N_NODES];
__device__ int   g_btot[64];
__device__ int   g_start[N_NODES + 1];
__device__ int   g_cur[N_NODES + 1];
__device__ int   g_scol[N_EDGES];
__device__ __align__(16) __half g_xh[N_NODES * DIM];   // fp16 mirror of x
__device__ __align__(16) __half g_w1t[HID * DIM];      // W1^T fp16: [n][k]

// ---------------------------------------------------------------------------
__device__ __forceinline__ int load_idx(const void* ei, long long pos, bool is64) {
    int v = is64 ? (int)((const long long*)ei)[pos] : ((const int*)ei)[pos];
    return min(max(v, 0), N_NODES - 1);
}

__device__ __forceinline__ void mma_f16(float* c, const unsigned* a,
                                        unsigned b0, unsigned b1) {
    asm volatile(
        "mma.sync.aligned.m16n8k16.row.col.f32.f16.f16.f32 "
        "{%0,%1,%2,%3}, {%4,%5,%6,%7}, {%8,%9}, {%0,%1,%2,%3};"
        : "+f"(c[0]), "+f"(c[1]), "+f"(c[2]), "+f"(c[3])
        : "r"(a[0]), "r"(a[1]), "r"(a[2]), "r"(a[3]), "r"(b0), "r"(b1));
}

// ---------------------------------------------------------------------------
__global__ void detect_kernel(const int* __restrict__ ei32) {
    int all_hi_zero = 1;
    #pragma unroll 8
    for (int i = 0; i < 512; ++i)
        if (ei32[2 * i + 1] != 0) { all_hi_zero = 0; break; }
    g_is64 = all_hi_zero;
}

__global__ void zero_cnt_kernel() {
    int i = blockIdx.x * blockDim.x + threadIdx.x;
    if (i < N_NODES) g_cnt[i] = 0;
}

// x -> fp16 mirror (for agg gathers)
__global__ void convert_x_kernel(const float4* __restrict__ x4) {
    const int total = N_NODES * (DIM / 4);
    int i = blockIdx.x * blockDim.x + threadIdx.x;
    if (i >= total) return;
    float4 v = __ldg(&x4[i]);
    __half2* dst = (__half2*)g_xh;
    dst[2 * i]     = __floats2half2_rn(v.x, v.y);
    dst[2 * i + 1] = __floats2half2_rn(v.z, v.w);
}

// W1 [k][n] fp32 -> W1^T fp16 [n][k] (B fragments become contiguous-k LDG.32s)
__global__ void prep_w1_kernel(const float* __restrict__ W1) {
    int i = blockIdx.x * blockDim.x + threadIdx.x;
    if (i >= HID * DIM) return;
    int n = i >> 8;
    int k = i & (DIM - 1);
    g_w1t[n * DIM + k] = __float2half_rn(W1[k * HID + n]);
}

// ---------------------------------------------------------------------------
// CSR build
// ---------------------------------------------------------------------------
__global__ void count_kernel(const void* __restrict__ ei) {
    int e = blockIdx.x * blockDim.x + threadIdx.x;
    if (e >= N_EDGES) return;
    int row = load_idx(ei, e, g_is64 != 0);
    atomicAdd(&g_cnt[row], 1);
}

__global__ void scan1_kernel() {
    __shared__ int s_wt[32];
    const int t = threadIdx.x, b = blockIdx.x;
    const int lane = t & 31, wid = t >> 5;
    const int i = b * SCAN_B + t;
    int sv = (i < N_NODES) ? g_cnt[i] : 0;
    #pragma unroll
    for (int off = 1; off < 32; off <<= 1) {
        int u = __shfl_up_sync(0xffffffffu, sv, off);
        if (lane >= off) sv += u;
    }
    if (lane == 31) s_wt[wid] = sv;
    __syncthreads();
    if (wid == 0) {
        int wv = s_wt[lane];
        #pragma unroll
        for (int off = 1; off < 32; off <<= 1) {
            int u = __shfl_up_sync(0xffffffffu, wv, off);
            if (lane >= off) wv += u;
        }
        s_wt[lane] = wv;
    }
    __syncthreads();
    int incl = sv + ((wid > 0) ? s_wt[wid - 1] : 0);
    if (i < N_NODES) g_incl[i] = incl;
    if (t == SCAN_B - 1) g_btot[b] = incl;
}

__global__ void scan2_kernel() {
    if (threadIdx.x == 0) {
        int run = 0;
        #pragma unroll 1
        for (int b = 0; b < NB_SCAN; ++b) {
            int t = g_btot[b];
            g_btot[b] = run;
            run += t;
        }
    }
}

__global__ void scan3_kernel() {
    int i = blockIdx.x * blockDim.x + threadIdx.x;
    if (i >= N_NODES) return;
    int v = g_incl[i] + g_btot[i >> 10];
    g_start[i + 1] = v;
    g_cur[i + 1]   = v;
    if (i == 0) { g_start[0] = 0; g_cur[0] = 0; }
}

__global__ void fill_kernel(const void* __restrict__ ei) {
    int e = blockIdx.x * blockDim.x + threadIdx.x;
    if (e >= N_EDGES) return;
    bool is64 = (g_is64 != 0);
    int row = load_idx(ei, e, is64);
    int col = load_idx(ei, (long long)N_EDGES + e, is64);
    int pos = atomicAdd(&g_cur[row], 1);
    g_scol[pos] = col;
}

// ---------------------------------------------------------------------------
// Node attention weights via SINGLE-product fp16 HMMA (mma.sync m16n8k16,
// f32 accumulate). R5 calibration: the 4-product split version ran ~113us,
// so 1 product + half the B loads ~= 30us. fp16 input error adds ~1e-4 to
// weight relative error -- inside budget (threshold 1e-3, currently 2.07e-4).
// Block = 64 nodes, 8 warps: 4 M-warps (16 rows) x 2 N-warps (64 hid cols).
// ---------------------------------------------------------------------------
__global__ __launch_bounds__(NTHR)
void node_weight_kernel(const float* __restrict__ x,
                        const float* __restrict__ b1,
                        const float* __restrict__ W2,
                        const float* __restrict__ b2)
{
    __shared__ __half sxh[TM * LDK];
    __shared__ float s_red[2][TM];
    __shared__ float s_b1[HID];
    __shared__ float s_w2[HID];

    const int tid  = threadIdx.x;
    const int lane = tid & 31;
    const int wid  = tid >> 5;
    const int wm   = wid >> 1;        // 0..3 -> rows [wm*16, +16)
    const int wn   = wid & 1;         // 0..1 -> hid cols [wn*64, +64)
    const int base = blockIdx.x * TM;

    if (tid < HID) {
        s_b1[tid] = __ldg(&b1[tid]);
        s_w2[tid] = __ldg(&W2[tid]);
    }

    // --- stage x tile: fp32 -> fp16 in smem ---
    #pragma unroll
    for (int it = 0; it < (TM * (DIM / 4)) / NTHR; ++it) {
        int f = it * NTHR + tid;
        int row = f >> 6;
        int q = f & 63;
        int node = min(base + row, N_NODES - 1);
        float4 v = __ldg(((const float4*)(x + (long long)node * DIM)) + q);
        __half2 h01 = __floats2half2_rn(v.x, v.y);
        __half2 h23 = __floats2half2_rn(v.z, v.w);
        __half2* o = (__half2*)&sxh[row * LDK + q * 4];
        o[0] = h01;
        o[1] = h23;
    }
    __syncthreads();

    // --- GEMM: 16 k-steps x 8 n-tiles, single product ---
    float acc[8][4];
    #pragma unroll
    for (int nt = 0; nt < 8; ++nt)
        #pragma unroll
        for (int c = 0; c < 4; ++c) acc[nt][c] = 0.f;

    const int r0  = wm * 16 + (lane >> 2);
    const int klo = (lane & 3) * 2;
    const unsigned* W1t32 = (const unsigned*)g_w1t;

    #pragma unroll 1
    for (int ks = 0; ks < DIM / 16; ++ks) {
        const int k = ks * 16 + klo;
        unsigned a[4];
        a[0] = *(const unsigned*)&sxh[r0 * LDK + k];
        a[1] = *(const unsigned*)&sxh[(r0 + 8) * LDK + k];
        a[2] = *(const unsigned*)&sxh[r0 * LDK + k + 8];
        a[3] = *(const unsigned*)&sxh[(r0 + 8) * LDK + k + 8];

        #pragma unroll
        for (int nt = 0; nt < 8; ++nt) {
            const int n0 = wn * 64 + nt * 8 + (lane >> 2);
            const int bo = (n0 * DIM + ks * 16 + klo) >> 1;   // uint32 index
            unsigned b0 = __ldg(&W1t32[bo]);
            unsigned b1r = __ldg(&W1t32[bo + 4]);
            mma_f16(acc[nt], a, b0, b1r);
        }
    }

    // --- epilogue: relu(+b1) . W2 per row, reduce lanes 1&2, then N-warps ---
    float sA = 0.f, sB = 0.f;
    #pragma unroll
    for (int nt = 0; nt < 8; ++nt) {
        int j0 = wn * 64 + nt * 8 + (lane & 3) * 2;
        float bb0 = s_b1[j0],  bb1 = s_b1[j0 + 1];
        float ww0 = s_w2[j0],  ww1 = s_w2[j0 + 1];
        sA = fmaf(fmaxf(acc[nt][0] + bb0, 0.f), ww0, sA);
        sA = fmaf(fmaxf(acc[nt][1] + bb1, 0.f), ww1, sA);
        sB = fmaf(fmaxf(acc[nt][2] + bb0, 0.f), ww0, sB);
        sB = fmaf(fmaxf(acc[nt][3] + bb1, 0.f), ww1, sB);
    }
    sA += __shfl_xor_sync(0xffffffffu, sA, 1);
    sA += __shfl_xor_sync(0xffffffffu, sA, 2);
    sB += __shfl_xor_sync(0xffffffffu, sB, 1);
    sB += __shfl_xor_sync(0xffffffffu, sB, 2);

    if ((lane & 3) == 0) {
        s_red[wn][wm * 16 + (lane >> 2)]     = sA;
        s_red[wn][wm * 16 + 8 + (lane >> 2)] = sB;
    }
    __syncthreads();

    if (tid < TM) {
        int node = base + tid;
        if (node < N_NODES) {
            float logit = s_red[0][tid] + s_red[1][tid] + __ldg(b2);
            g_wnode[node] = 1.f / (1.f + expf(-logit));
        }
    }
}

// ---------------------------------------------------------------------------
// Aggregation: one warp per destination node, fp16 gather, fp32 accumulate.
// ---------------------------------------------------------------------------
__global__ __launch_bounds__(NTHR, 8)
void agg_kernel(float* __restrict__ out)
{
    const int warp = (blockIdx.x * NTHR + threadIdx.x) >> 5;
    const int lane = threadIdx.x & 31;
    if (warp >= N_NODES) return;

    const int s = g_start[warp];
    const int e = g_start[warp + 1];

    float acc[8] = {0.f, 0.f, 0.f, 0.f, 0.f, 0.f, 0.f, 0.f};
    float wsum = 0.f;

    for (int base = s; base < e; base += 32) {
        const int n = min(32, e - base);
        int   col = 0;
        float wv  = 0.f;
        if (lane < n) {
            col = g_scol[base + lane];
            wv  = __ldg(&g_wnode[col]);
        }
        for (int c = 0; c < n; ++c) {
            int   cc = __shfl_sync(0xffffffffu, col, c);
            float ww = __shfl_sync(0xffffffffu, wv,  c);
            const uint4* src = (const uint4*)(g_xh + (long long)cc * DIM);
            uint4 p = __ldg(src + lane);          // 8 halfs
            float2 f0 = __half22float2(*(const __half2*)&p.x);
            float2 f1 = __half22float2(*(const __half2*)&p.y);
            float2 f2 = __half22float2(*(const __half2*)&p.z);
            float2 f3 = __half22float2(*(const __half2*)&p.w);
            acc[0] = fmaf(ww, f0.x, acc[0]);
            acc[1] = fmaf(ww, f0.y, acc[1]);
            acc[2] = fmaf(ww, f1.x, acc[2]);
            acc[3] = fmaf(ww, f1.y, acc[3]);
            acc[4] = fmaf(ww, f2.x, acc[4]);
            acc[5] = fmaf(ww, f2.y, acc[5]);
            acc[6] = fmaf(ww, f3.x, acc[6]);
            acc[7] = fmaf(ww, f3.y, acc[7]);
            wsum += ww;
        }
    }

    float4* dst = (float4*)(out + (long long)warp * DIM) + lane * 2;
    if (e > s) {
        float inv = 1.f / fmaxf(wsum, 1e-12f);
        dst[0] = make_float4(acc[0] * inv, acc[1] * inv, acc[2] * inv, acc[3] * inv);
        dst[1] = make_float4(acc[4] * inv, acc[5] * inv, acc[6] * inv, acc[7] * inv);
    } else {
        float4 z = make_float4(0.f, 0.f, 0.f, 0.f);
        dst[0] = z;
        dst[1] = z;
    }
}

// ---------------------------------------------------------------------------
extern "C" void kernel_launch(void* const* d_in, const int* in_sizes, int n_in,
                              void* d_out, int out_size) {
    const float* x   = (const float*)d_in[0];
    const void*  ei  = d_in[1];
    const float* W1  = (const float*)d_in[2];
    const float* b1  = (const float*)d_in[3];
    const float* W2  = (const float*)d_in[4];
    const float* b2  = (const float*)d_in[5];
    float*       out = (float*)d_out;

    static cudaStream_t s_side = nullptr;
    static cudaEvent_t  ev_fork = nullptr, ev_join = nullptr;
    if (!s_side) {
        cudaStreamCreateWithFlags(&s_side, cudaStreamNonBlocking);
        cudaEventCreateWithFlags(&ev_fork, cudaEventDisableTiming);
        cudaEventCreateWithFlags(&ev_join, cudaEventDisableTiming);
    }

    cudaEventRecord(ev_fork, 0);
    cudaStreamWaitEvent(s_side, ev_fork, 0);

    // side stream: fp16 mirror of x, then CSR build
    const int total4 = N_NODES * (DIM / 4);
    convert_x_kernel<<<(total4 + 255) / 256, 256, 0, s_side>>>((const float4*)x);
    detect_kernel<<<1, 1, 0, s_side>>>((const int*)ei);
    zero_cnt_kernel<<<(N_NODES + 255) / 256, 256, 0, s_side>>>();
    count_kernel<<<(N_EDGES + NTHR - 1) / NTHR, NTHR, 0, s_side>>>(ei);
    scan1_kernel<<<NB_SCAN, SCAN_B, 0, s_side>>>();
    scan2_kernel<<<1, 32, 0, s_side>>>();
    scan3_kernel<<<(N_NODES + 255) / 256, 256, 0, s_side>>>();
    fill_kernel<<<(N_EDGES + NTHR - 1) / NTHR, NTHR, 0, s_side>>>(ei);
    cudaEventRecord(ev_join, s_side);

    // main stream: W1 -> fp16 transpose, then HMMA node weights
    prep_w1_kernel<<<(HID * DIM + 255) / 256, 256>>>(W1);
    const int nw_blocks = (N_NODES + TM - 1) / TM;   // 782
    node_weight_kernel<<<nw_blocks, NTHR>>>(x, b1, W2, b2);

    cudaStreamWaitEvent(0, ev_join, 0);
    const int agg_blocks = (N_NODES * 32 + NTHR - 1) / NTHR;  // 6250
    agg_kernel<<<agg_blocks, NTHR>>>(out);
}